// round 1
// baseline (speedup 1.0000x reference)
#include <cuda_runtime.h>
#include <cuda_bf16.h>
#include <cstddef>

// ---------------- constants ----------------
#define T_TOK   4096
#define HID     2048
#define NH      16
#define NKV     4
#define HD      128
#define INTER   8192
#define BATCH   4
#define SEQ     1024
#define QKVW    3072   // 2048 q + 512 k + 512 v
#define EPSV    1e-6f

// ---------------- scratch (__device__ globals; no allocs allowed) ----------------
__device__ float g_h1  [(size_t)T_TOK * HID];    // rmsnorm1 output / reused as h2
__device__ float g_qkv [(size_t)T_TOK * QKVW];
__device__ float g_attn[(size_t)T_TOK * HID];
__device__ float g_x1  [(size_t)T_TOK * HID];    // x + attn@wo
__device__ float g_gate[(size_t)T_TOK * INTER];  // gate, then silu(gate)*up in-place
__device__ float g_up  [(size_t)T_TOK * INTER];

// ---------------- rmsnorm over 2048 cols ----------------
__global__ __launch_bounds__(256) void rmsnorm2048(const float* __restrict__ x,
                                                   const float* __restrict__ w,
                                                   float* __restrict__ y) {
    int row = blockIdx.x;
    const float* xr = x + (size_t)row * HID;
    int t = threadIdx.x;
    float vals[8];
    float ss = 0.f;
#pragma unroll
    for (int i = 0; i < 8; i++) { float v = xr[t + i * 256]; vals[i] = v; ss += v * v; }
#pragma unroll
    for (int o = 16; o > 0; o >>= 1) ss += __shfl_xor_sync(0xffffffffu, ss, o);
    __shared__ float red[8];
    __shared__ float srs;
    if ((t & 31) == 0) red[t >> 5] = ss;
    __syncthreads();
    if (t == 0) {
        float s = 0.f;
#pragma unroll
        for (int i = 0; i < 8; i++) s += red[i];
        srs = rsqrtf(s / (float)HID + EPSV);
    }
    __syncthreads();
    float r = srs;
    float* yr = y + (size_t)row * HID;
#pragma unroll
    for (int i = 0; i < 8; i++) { int c = t + i * 256; yr[c] = vals[i] * r * w[c]; }
}

// ---------------- per-head rmsnorm + RoPE (in place on qkv) ----------------
__global__ __launch_bounds__(128) void qknorm_rope(float* __restrict__ qkv,
                                                   const float* __restrict__ qnw,
                                                   const float* __restrict__ knw,
                                                   const float* __restrict__ cosT,
                                                   const float* __restrict__ sinT) {
    int tok = blockIdx.x;
    int hh  = blockIdx.y;          // 0..15 = q heads, 16..19 = k heads
    int d   = threadIdx.x;         // 0..127
    float* base = qkv + (size_t)tok * QKVW + (hh < NH ? hh * HD : HID + (hh - NH) * HD);
    const float* nw = (hh < NH) ? qnw : knw;
    float v = base[d];
    float ss = v * v;
#pragma unroll
    for (int o = 16; o > 0; o >>= 1) ss += __shfl_xor_sync(0xffffffffu, ss, o);
    __shared__ float red[4];
    __shared__ float rtot;
    if ((d & 31) == 0) red[d >> 5] = ss;
    __syncthreads();
    if (d == 0) rtot = rsqrtf((red[0] + red[1] + red[2] + red[3]) / (float)HD + EPSV);
    __syncthreads();
    float n = v * rtot * nw[d];
    __shared__ float sn[HD];
    sn[d] = n;
    __syncthreads();
    const float* c = cosT + (size_t)tok * HD;
    const float* s = sinT + (size_t)tok * HD;
    float out = (d < 64) ? (n * c[d] - sn[d + 64] * s[d])
                         : (n * c[d] + sn[d - 64] * s[d]);
    base[d] = out;
}

// ---------------- flash attention (64q x 64k tiles, online softmax) ----------------
// grid (B*H, SEQ/64), 128 threads. smem strides 129/132/65 chosen for bank behavior.
#define QS_STRIDE 129
#define KS_STRIDE 129
#define VS_STRIDE 132
#define SS_STRIDE 65
#define ATTN_SMEM ((64*QS_STRIDE + 64*KS_STRIDE + 64*VS_STRIDE + 64*SS_STRIDE) * 4)

__global__ __launch_bounds__(128) void attn_kernel(const float* __restrict__ qkv,
                                                   float* __restrict__ attn) {
    extern __shared__ float sm[];
    float* Qs = sm;
    float* Ks = Qs + 64 * QS_STRIDE;
    float* Vs = Ks + 64 * KS_STRIDE;
    float* Ss = Vs + 64 * VS_STRIDE;
    int tid = threadIdx.x;
    int bh = blockIdx.x;            // 0..63
    int qt = blockIdx.y;            // 0..15
    int b = bh >> 4, h = bh & 15, kvh = h >> 2;
    int tok0 = b * SEQ + qt * 64;

    // load Q tile [64 x 128]
    for (int i = tid; i < 2048; i += 128) {
        int r = i >> 5, c = (i & 31) << 2;
        float4 v = *(const float4*)(qkv + (size_t)(tok0 + r) * QKVW + h * HD + c);
        float* q = Qs + r * QS_STRIDE + c;
        q[0] = v.x; q[1] = v.y; q[2] = v.z; q[3] = v.w;
    }

    int qi  = (tid >> 3) << 2;      // 4 query rows per 8-thread group
    int ki8 = (tid & 7) << 3;       // 8 keys in score phase
    int di  = (tid & 7) << 4;       // 16 dims in PV phase
    float m[4], l[4], acc[4][16];
#pragma unroll
    for (int a = 0; a < 4; a++) {
        m[a] = -1e30f; l[a] = 0.f;
#pragma unroll
        for (int dd = 0; dd < 16; dd++) acc[a][dd] = 0.f;
    }
    const float scale = 0.08838834764831845f;  // 1/sqrt(128)

    for (int kt = 0; kt <= qt; kt++) {
        // load K and V tiles
        for (int i = tid; i < 2048; i += 128) {
            int r = i >> 5, c = (i & 31) << 2;
            const float* kp = qkv + (size_t)(b * SEQ + kt * 64 + r) * QKVW + HID + kvh * HD + c;
            float4 kv = *(const float4*)kp;
            float* kd = Ks + r * KS_STRIDE + c;
            kd[0] = kv.x; kd[1] = kv.y; kd[2] = kv.z; kd[3] = kv.w;
            float4 vv = *(const float4*)(kp + NKV * HD);  // v block is +512 floats
            *(float4*)(Vs + r * VS_STRIDE + c) = vv;
        }
        __syncthreads();

        // scores: 4x8 microtile, K=128
        float s[4][8];
#pragma unroll
        for (int a = 0; a < 4; a++)
#pragma unroll
            for (int kb = 0; kb < 8; kb++) s[a][kb] = 0.f;
        for (int kk = 0; kk < HD; kk++) {
            float qv[4], kv[8];
#pragma unroll
            for (int a = 0; a < 4; a++) qv[a] = Qs[(qi + a) * QS_STRIDE + kk];
#pragma unroll
            for (int kb = 0; kb < 8; kb++) kv[kb] = Ks[(ki8 + kb) * KS_STRIDE + kk];
#pragma unroll
            for (int a = 0; a < 4; a++)
#pragma unroll
                for (int kb = 0; kb < 8; kb++) s[a][kb] += qv[a] * kv[kb];
        }

        // mask + scale + online softmax stats
        float mnew[4], corr[4];
#pragma unroll
        for (int a = 0; a < 4; a++) {
            int qg = qt * 64 + qi + a;
            float tmax = -1e30f;
#pragma unroll
            for (int kb = 0; kb < 8; kb++) {
                int kg = kt * 64 + ki8 + kb;
                float v = (kg <= qg) ? s[a][kb] * scale : -1e30f;
                s[a][kb] = v;
                tmax = fmaxf(tmax, v);
            }
#pragma unroll
            for (int o = 1; o < 8; o <<= 1) tmax = fmaxf(tmax, __shfl_xor_sync(0xffffffffu, tmax, o));
            mnew[a] = fmaxf(m[a], tmax);
            corr[a] = __expf(m[a] - mnew[a]);
            m[a] = mnew[a];
        }
#pragma unroll
        for (int a = 0; a < 4; a++) {
            float ps = 0.f;
#pragma unroll
            for (int kb = 0; kb < 8; kb++) {
                float p = __expf(s[a][kb] - mnew[a]);
                Ss[(qi + a) * SS_STRIDE + ki8 + kb] = p;
                ps += p;
            }
#pragma unroll
            for (int o = 1; o < 8; o <<= 1) ps += __shfl_xor_sync(0xffffffffu, ps, o);
            l[a] = l[a] * corr[a] + ps;
#pragma unroll
            for (int dd = 0; dd < 16; dd++) acc[a][dd] *= corr[a];
        }
        __syncthreads();

        // PV: 4q x 16d microtile over 64 keys
        for (int k = 0; k < 64; k++) {
            float pv[4];
#pragma unroll
            for (int a = 0; a < 4; a++) pv[a] = Ss[(qi + a) * SS_STRIDE + k];
#pragma unroll
            for (int dd = 0; dd < 16; dd++) {
                float vv = Vs[k * VS_STRIDE + di + dd];
#pragma unroll
                for (int a = 0; a < 4; a++) acc[a][dd] += pv[a] * vv;
            }
        }
        __syncthreads();
    }

#pragma unroll
    for (int a = 0; a < 4; a++) {
        float inv = 1.f / l[a];
        float* o = attn + (size_t)(tok0 + qi + a) * HID + h * HD + di;
#pragma unroll
        for (int dd = 0; dd < 16; dd++) o[dd] = acc[a][dd] * inv;
    }
}

// ---------------- SGEMM: C[M,N] = A[M,K] @ W[N,K]^T (+bias)(+res) ----------------
// 128x128 tile, BK=8, 256 threads, 8x8 microtile. grid = (N/128, M/128).
__global__ __launch_bounds__(256) void sgemm128(const float* __restrict__ A,
                                                const float* __restrict__ W,
                                                const float* __restrict__ bias,
                                                const float* __restrict__ res,
                                                float* __restrict__ C,
                                                int K, int ldc) {
    __shared__ float As[8][128];
    __shared__ float Ws[8][128];
    int tid = threadIdx.x;
    size_t bm = (size_t)blockIdx.y * 128;
    size_t bn = (size_t)blockIdx.x * 128;
    int lr = tid >> 1;
    int lc = (tid & 1) * 4;
    const float* Ap = A + (bm + lr) * (size_t)K + lc;
    const float* Wp = W + (bn + lr) * (size_t)K + lc;
    int tr = (tid >> 4) * 8;
    int tc = (tid & 15) * 8;
    float acc[8][8];
#pragma unroll
    for (int i = 0; i < 8; i++)
#pragma unroll
        for (int j = 0; j < 8; j++) acc[i][j] = 0.f;

    for (int k0 = 0; k0 < K; k0 += 8) {
        float4 a = *(const float4*)(Ap + k0);
        float4 w = *(const float4*)(Wp + k0);
        As[lc + 0][lr] = a.x; As[lc + 1][lr] = a.y; As[lc + 2][lr] = a.z; As[lc + 3][lr] = a.w;
        Ws[lc + 0][lr] = w.x; Ws[lc + 1][lr] = w.y; Ws[lc + 2][lr] = w.z; Ws[lc + 3][lr] = w.w;
        __syncthreads();
#pragma unroll
        for (int kk = 0; kk < 8; kk++) {
            float4 a0 = *(const float4*)&As[kk][tr];
            float4 a1 = *(const float4*)&As[kk][tr + 4];
            float4 b0 = *(const float4*)&Ws[kk][tc];
            float4 b1 = *(const float4*)&Ws[kk][tc + 4];
            float ra[8] = {a0.x, a0.y, a0.z, a0.w, a1.x, a1.y, a1.z, a1.w};
            float rb[8] = {b0.x, b0.y, b0.z, b0.w, b1.x, b1.y, b1.z, b1.w};
#pragma unroll
            for (int i = 0; i < 8; i++)
#pragma unroll
                for (int j = 0; j < 8; j++) acc[i][j] += ra[i] * rb[j];
        }
        __syncthreads();
    }

#pragma unroll
    for (int i = 0; i < 8; i++) {
        size_t row = bm + tr + i;
#pragma unroll
        for (int j = 0; j < 8; j++) {
            size_t col = bn + tc + j;
            float v = acc[i][j];
            if (bias) v += bias[col];
            if (res) v += res[row * (size_t)ldc + col];
            C[row * (size_t)ldc + col] = v;
        }
    }
}

// ---------------- silu(gate) * up, in place in gate ----------------
__global__ __launch_bounds__(256) void silu_mul(float* __restrict__ g,
                                                const float* __restrict__ u, int n) {
    int i = blockIdx.x * 256 + threadIdx.x;
    if (i < n) {
        float x = g[i];
        float s = 1.f / (1.f + expf(-x));
        g[i] = x * s * u[i];
    }
}

// ---------------- launch ----------------
extern "C" void kernel_launch(void* const* d_in, const int* in_sizes, int n_in,
                              void* d_out, int out_size) {
    const float* x    = (const float*)d_in[0];
    // d_in[1] = attention_mask (causal, known statically) — unused
    const float* cosT = (const float*)d_in[2];
    const float* sinT = (const float*)d_in[3];
    const float* wq   = (const float*)d_in[4];
    const float* bq   = (const float*)d_in[5];
    const float* wk   = (const float*)d_in[6];
    const float* bk   = (const float*)d_in[7];
    const float* wv   = (const float*)d_in[8];
    const float* bv   = (const float*)d_in[9];
    const float* wo   = (const float*)d_in[10];
    const float* qnw  = (const float*)d_in[11];
    const float* knw  = (const float*)d_in[12];
    const float* ln1  = (const float*)d_in[13];
    const float* ln2  = (const float*)d_in[14];
    const float* wg   = (const float*)d_in[15];
    const float* wu   = (const float*)d_in[16];
    const float* wd   = (const float*)d_in[17];
    float* out = (float*)d_out;

    void *ph1, *pqkv, *pattn, *px1, *pgate, *pup;
    cudaGetSymbolAddress(&ph1,  g_h1);
    cudaGetSymbolAddress(&pqkv, g_qkv);
    cudaGetSymbolAddress(&pattn,g_attn);
    cudaGetSymbolAddress(&px1,  g_x1);
    cudaGetSymbolAddress(&pgate,g_gate);
    cudaGetSymbolAddress(&pup,  g_up);
    float* h1   = (float*)ph1;
    float* qkv  = (float*)pqkv;
    float* attn = (float*)pattn;
    float* x1   = (float*)px1;
    float* gate = (float*)pgate;
    float* up   = (float*)pup;

    cudaFuncSetAttribute(attn_kernel, cudaFuncAttributeMaxDynamicSharedMemorySize, ATTN_SMEM);

    // 1. rmsnorm1
    rmsnorm2048<<<T_TOK, 256>>>(x, ln1, h1);
    // 2. QKV projections into one [T, 3072] buffer
    sgemm128<<<dim3(HID / 128, T_TOK / 128), 256>>>(h1, wq, bq, nullptr, qkv,            HID, QKVW);
    sgemm128<<<dim3(512 / 128, T_TOK / 128), 256>>>(h1, wk, bk, nullptr, qkv + HID,      HID, QKVW);
    sgemm128<<<dim3(512 / 128, T_TOK / 128), 256>>>(h1, wv, bv, nullptr, qkv + HID + 512,HID, QKVW);
    // 3. per-head rmsnorm + rope (q and k heads)
    qknorm_rope<<<dim3(T_TOK, NH + NKV), 128>>>(qkv, qnw, knw, cosT, sinT);
    // 4. attention
    attn_kernel<<<dim3(BATCH * NH, SEQ / 64), 128, ATTN_SMEM>>>(qkv, attn);
    // 5. o-proj + residual -> x1
    sgemm128<<<dim3(HID / 128, T_TOK / 128), 256>>>(attn, wo, nullptr, x, x1, HID, HID);
    // 6. rmsnorm2 (reuse h1)
    rmsnorm2048<<<T_TOK, 256>>>(x1, ln2, h1);
    // 7. gate/up projections
    sgemm128<<<dim3(INTER / 128, T_TOK / 128), 256>>>(h1, wg, nullptr, nullptr, gate, HID, INTER);
    sgemm128<<<dim3(INTER / 128, T_TOK / 128), 256>>>(h1, wu, nullptr, nullptr, up,   HID, INTER);
    // 8. silu(gate) * up
    silu_mul<<<(T_TOK * INTER) / 256, 256>>>(gate, up, T_TOK * INTER);
    // 9. down-proj + residual -> out
    sgemm128<<<dim3(HID / 128, T_TOK / 128), 256>>>(gate, wd, nullptr, x1, out, INTER, HID);
}

// round 2
// speedup vs baseline: 2.5201x; 2.5201x over previous
#include <cuda_runtime.h>
#include <cuda_bf16.h>
#include <cstddef>
#include <cstdint>

// ---------------- constants ----------------
#define T_TOK   4096
#define HID     2048
#define NH      16
#define NKV     4
#define HD      128
#define INTER   8192
#define BATCH   4
#define SEQ     1024
#define QKVW    3072   // 2048 q + 512 k + 512 v
#define EPSV    1e-6f

// ---------------- scratch (__device__ globals; no allocs allowed) ----------------
__device__ float g_h1  [(size_t)T_TOK * HID];    // rmsnorm1 output / reused as h2
__device__ float g_qkv [(size_t)T_TOK * QKVW];
__device__ float g_attn[(size_t)T_TOK * HID];
__device__ float g_x1  [(size_t)T_TOK * HID];    // x + attn@wo
__device__ float g_gate[(size_t)T_TOK * INTER];  // gate, then silu(gate)*up in-place
__device__ float g_up  [(size_t)T_TOK * INTER];

// ---------------- rmsnorm over 2048 cols ----------------
__global__ __launch_bounds__(256) void rmsnorm2048(const float* __restrict__ x,
                                                   const float* __restrict__ w,
                                                   float* __restrict__ y) {
    int row = blockIdx.x;
    const float* xr = x + (size_t)row * HID;
    int t = threadIdx.x;
    float vals[8];
    float ss = 0.f;
#pragma unroll
    for (int i = 0; i < 8; i++) { float v = xr[t + i * 256]; vals[i] = v; ss += v * v; }
#pragma unroll
    for (int o = 16; o > 0; o >>= 1) ss += __shfl_xor_sync(0xffffffffu, ss, o);
    __shared__ float red[8];
    __shared__ float srs;
    if ((t & 31) == 0) red[t >> 5] = ss;
    __syncthreads();
    if (t == 0) {
        float s = 0.f;
#pragma unroll
        for (int i = 0; i < 8; i++) s += red[i];
        srs = rsqrtf(s / (float)HID + EPSV);
    }
    __syncthreads();
    float r = srs;
    float* yr = y + (size_t)row * HID;
#pragma unroll
    for (int i = 0; i < 8; i++) { int c = t + i * 256; yr[c] = vals[i] * r * w[c]; }
}

// ---------------- per-head rmsnorm + RoPE (in place on qkv) ----------------
__global__ __launch_bounds__(128) void qknorm_rope(float* __restrict__ qkv,
                                                   const float* __restrict__ qnw,
                                                   const float* __restrict__ knw,
                                                   const float* __restrict__ cosT,
                                                   const float* __restrict__ sinT) {
    int tok = blockIdx.x;
    int hh  = blockIdx.y;          // 0..15 = q heads, 16..19 = k heads
    int d   = threadIdx.x;         // 0..127
    float* base = qkv + (size_t)tok * QKVW + (hh < NH ? hh * HD : HID + (hh - NH) * HD);
    const float* nw = (hh < NH) ? qnw : knw;
    float v = base[d];
    float ss = v * v;
#pragma unroll
    for (int o = 16; o > 0; o >>= 1) ss += __shfl_xor_sync(0xffffffffu, ss, o);
    __shared__ float red[4];
    __shared__ float rtot;
    if ((d & 31) == 0) red[d >> 5] = ss;
    __syncthreads();
    if (d == 0) rtot = rsqrtf((red[0] + red[1] + red[2] + red[3]) / (float)HD + EPSV);
    __syncthreads();
    float n = v * rtot * nw[d];
    __shared__ float sn[HD];
    sn[d] = n;
    __syncthreads();
    const float* c = cosT + (size_t)tok * HD;
    const float* s = sinT + (size_t)tok * HD;
    float out = (d < 64) ? (n * c[d] - sn[d + 64] * s[d])
                         : (n * c[d] + sn[d - 64] * s[d]);
    base[d] = out;
}

// ---------------- flash attention (64q x 64k tiles, online softmax) ----------------
#define QS_STRIDE 129
#define KS_STRIDE 129
#define VS_STRIDE 132
#define SS_STRIDE 65
#define ATTN_SMEM ((64*QS_STRIDE + 64*KS_STRIDE + 64*VS_STRIDE + 64*SS_STRIDE) * 4)

__global__ __launch_bounds__(128) void attn_kernel(const float* __restrict__ qkv,
                                                   float* __restrict__ attn) {
    extern __shared__ float sm[];
    float* Qs = sm;
    float* Ks = Qs + 64 * QS_STRIDE;
    float* Vs = Ks + 64 * KS_STRIDE;
    float* Ss = Vs + 64 * VS_STRIDE;
    int tid = threadIdx.x;
    int bh = blockIdx.x;            // 0..63
    int qt = blockIdx.y;            // 0..15
    int b = bh >> 4, h = bh & 15, kvh = h >> 2;
    int tok0 = b * SEQ + qt * 64;

    for (int i = tid; i < 2048; i += 128) {
        int r = i >> 5, c = (i & 31) << 2;
        float4 v = *(const float4*)(qkv + (size_t)(tok0 + r) * QKVW + h * HD + c);
        float* q = Qs + r * QS_STRIDE + c;
        q[0] = v.x; q[1] = v.y; q[2] = v.z; q[3] = v.w;
    }

    int qi  = (tid >> 3) << 2;
    int ki8 = (tid & 7) << 3;
    int di  = (tid & 7) << 4;
    float m[4], l[4], acc[4][16];
#pragma unroll
    for (int a = 0; a < 4; a++) {
        m[a] = -1e30f; l[a] = 0.f;
#pragma unroll
        for (int dd = 0; dd < 16; dd++) acc[a][dd] = 0.f;
    }
    const float scale = 0.08838834764831845f;

    for (int kt = 0; kt <= qt; kt++) {
        for (int i = tid; i < 2048; i += 128) {
            int r = i >> 5, c = (i & 31) << 2;
            const float* kp = qkv + (size_t)(b * SEQ + kt * 64 + r) * QKVW + HID + kvh * HD + c;
            float4 kv = *(const float4*)kp;
            float* kd = Ks + r * KS_STRIDE + c;
            kd[0] = kv.x; kd[1] = kv.y; kd[2] = kv.z; kd[3] = kv.w;
            float4 vv = *(const float4*)(kp + NKV * HD);
            *(float4*)(Vs + r * VS_STRIDE + c) = vv;
        }
        __syncthreads();

        float s[4][8];
#pragma unroll
        for (int a = 0; a < 4; a++)
#pragma unroll
            for (int kb = 0; kb < 8; kb++) s[a][kb] = 0.f;
        for (int kk = 0; kk < HD; kk++) {
            float qv[4], kv[8];
#pragma unroll
            for (int a = 0; a < 4; a++) qv[a] = Qs[(qi + a) * QS_STRIDE + kk];
#pragma unroll
            for (int kb = 0; kb < 8; kb++) kv[kb] = Ks[(ki8 + kb) * KS_STRIDE + kk];
#pragma unroll
            for (int a = 0; a < 4; a++)
#pragma unroll
                for (int kb = 0; kb < 8; kb++) s[a][kb] += qv[a] * kv[kb];
        }

        float mnew[4], corr[4];
#pragma unroll
        for (int a = 0; a < 4; a++) {
            int qg = qt * 64 + qi + a;
            float tmax = -1e30f;
#pragma unroll
            for (int kb = 0; kb < 8; kb++) {
                int kg = kt * 64 + ki8 + kb;
                float v = (kg <= qg) ? s[a][kb] * scale : -1e30f;
                s[a][kb] = v;
                tmax = fmaxf(tmax, v);
            }
#pragma unroll
            for (int o = 1; o < 8; o <<= 1) tmax = fmaxf(tmax, __shfl_xor_sync(0xffffffffu, tmax, o));
            mnew[a] = fmaxf(m[a], tmax);
            corr[a] = __expf(m[a] - mnew[a]);
            m[a] = mnew[a];
        }
#pragma unroll
        for (int a = 0; a < 4; a++) {
            float ps = 0.f;
#pragma unroll
            for (int kb = 0; kb < 8; kb++) {
                float p = __expf(s[a][kb] - mnew[a]);
                Ss[(qi + a) * SS_STRIDE + ki8 + kb] = p;
                ps += p;
            }
#pragma unroll
            for (int o = 1; o < 8; o <<= 1) ps += __shfl_xor_sync(0xffffffffu, ps, o);
            l[a] = l[a] * corr[a] + ps;
#pragma unroll
            for (int dd = 0; dd < 16; dd++) acc[a][dd] *= corr[a];
        }
        __syncthreads();

        for (int k = 0; k < 64; k++) {
            float pv[4];
#pragma unroll
            for (int a = 0; a < 4; a++) pv[a] = Ss[(qi + a) * SS_STRIDE + k];
#pragma unroll
            for (int dd = 0; dd < 16; dd++) {
                float vv = Vs[k * VS_STRIDE + di + dd];
#pragma unroll
                for (int a = 0; a < 4; a++) acc[a][dd] += pv[a] * vv;
            }
        }
        __syncthreads();
    }

#pragma unroll
    for (int a = 0; a < 4; a++) {
        float inv = 1.f / l[a];
        float* o = attn + (size_t)(tok0 + qi + a) * HID + h * HD + di;
#pragma unroll
        for (int dd = 0; dd < 16; dd++) o[dd] = acc[a][dd] * inv;
    }
}

// ---------------- TF32 tensor-core GEMM: C[M,N] = A[M,K] @ W[N,K]^T (+bias)(+res) ----------------
// 128x128 CTA tile, BK=32, 256 threads (8 warps in 2x4), warp tile 64x32,
// mma.sync.m16n8k8 tf32, double-buffered smem, stride-36 pad (conflict-free frags).

#define GBM 128
#define GBN 128
#define GBK 32
#define KST 36
#define TGEMM_SMEM (4 * GBM * KST * 4)   // 2 buffers * (A + W) * 128*36 floats

__device__ __forceinline__ float cvt_tf32(float x) {
    uint32_t u;
    asm("cvt.rna.tf32.f32 %0, %1;" : "=r"(u) : "f"(x));
    return __uint_as_float(u);
}

__device__ __forceinline__ void mma_tf32(float* c, const uint32_t* a, const uint32_t* b) {
    asm volatile("mma.sync.aligned.m16n8k8.row.col.f32.tf32.tf32.f32 "
                 "{%0,%1,%2,%3}, {%4,%5,%6,%7}, {%8,%9}, {%0,%1,%2,%3};"
                 : "+f"(c[0]), "+f"(c[1]), "+f"(c[2]), "+f"(c[3])
                 : "r"(a[0]), "r"(a[1]), "r"(a[2]), "r"(a[3]), "r"(b[0]), "r"(b[1]));
}

__global__ __launch_bounds__(256) void tgemm(const float* __restrict__ A,
                                             const float* __restrict__ W,
                                             const float* __restrict__ bias,
                                             const float* __restrict__ res,
                                             float* __restrict__ C,
                                             int K, int ldc) {
    extern __shared__ float sm[];
    float (*As)[GBM][KST] = (float (*)[GBM][KST])sm;                 // [2][128][36]
    float (*Ws)[GBM][KST] = (float (*)[GBM][KST])(sm + 2 * GBM * KST);

    int tid = threadIdx.x;
    int lane = tid & 31;
    int warp = tid >> 5;
    int warpM = (warp >> 2) * 64;   // 2 warps along M
    int warpN = (warp & 3) * 32;    // 4 warps along N
    size_t bm = (size_t)blockIdx.y * GBM;
    size_t bn = (size_t)blockIdx.x * GBN;

    // per-thread load coords: 4 float4 each for A and W chunks (128 rows x 32 cols)
    int lrow[4], lcol[4];
#pragma unroll
    for (int i = 0; i < 4; i++) {
        int v = tid + i * 256;
        lrow[i] = v >> 3;
        lcol[i] = (v & 7) * 4;
    }

    float acc[4][4][4];
#pragma unroll
    for (int mt = 0; mt < 4; mt++)
#pragma unroll
        for (int nt = 0; nt < 4; nt++)
#pragma unroll
            for (int j = 0; j < 4; j++) acc[mt][nt][j] = 0.f;

    // prologue: load chunk 0 into buffer 0
    float4 rA[4], rB[4];
#pragma unroll
    for (int i = 0; i < 4; i++) {
        rA[i] = *(const float4*)(A + (bm + lrow[i]) * (size_t)K + lcol[i]);
        rB[i] = *(const float4*)(W + (bn + lrow[i]) * (size_t)K + lcol[i]);
    }
#pragma unroll
    for (int i = 0; i < 4; i++) {
        float* ad = &As[0][lrow[i]][lcol[i]];
        ad[0] = cvt_tf32(rA[i].x); ad[1] = cvt_tf32(rA[i].y);
        ad[2] = cvt_tf32(rA[i].z); ad[3] = cvt_tf32(rA[i].w);
        float* wd = &Ws[0][lrow[i]][lcol[i]];
        wd[0] = cvt_tf32(rB[i].x); wd[1] = cvt_tf32(rB[i].y);
        wd[2] = cvt_tf32(rB[i].z); wd[3] = cvt_tf32(rB[i].w);
    }
    __syncthreads();

    int nchunk = K / GBK;
    for (int c = 0; c < nchunk; c++) {
        int cur = c & 1;
        int nxt = cur ^ 1;
        if (c + 1 < nchunk) {
            int k0 = (c + 1) * GBK;
#pragma unroll
            for (int i = 0; i < 4; i++) {
                rA[i] = *(const float4*)(A + (bm + lrow[i]) * (size_t)K + k0 + lcol[i]);
                rB[i] = *(const float4*)(W + (bn + lrow[i]) * (size_t)K + k0 + lcol[i]);
            }
        }

        // compute on buffer cur: 4 k-steps of 8
#pragma unroll
        for (int ks = 0; ks < 4; ks++) {
            int kb = ks * 8;
            uint32_t af[4][4], bf[4][2];
#pragma unroll
            for (int mt = 0; mt < 4; mt++) {
                int r = warpM + mt * 16 + (lane >> 2);
                int kc = kb + (lane & 3);
                af[mt][0] = __float_as_uint(As[cur][r][kc]);
                af[mt][1] = __float_as_uint(As[cur][r + 8][kc]);
                af[mt][2] = __float_as_uint(As[cur][r][kc + 4]);
                af[mt][3] = __float_as_uint(As[cur][r + 8][kc + 4]);
            }
#pragma unroll
            for (int nt = 0; nt < 4; nt++) {
                int n = warpN + nt * 8 + (lane >> 2);
                int kc = kb + (lane & 3);
                bf[nt][0] = __float_as_uint(Ws[cur][n][kc]);
                bf[nt][1] = __float_as_uint(Ws[cur][n][kc + 4]);
            }
#pragma unroll
            for (int mt = 0; mt < 4; mt++)
#pragma unroll
                for (int nt = 0; nt < 4; nt++)
                    mma_tf32(acc[mt][nt], af[mt], bf[nt]);
        }

        if (c + 1 < nchunk) {
#pragma unroll
            for (int i = 0; i < 4; i++) {
                float* ad = &As[nxt][lrow[i]][lcol[i]];
                ad[0] = cvt_tf32(rA[i].x); ad[1] = cvt_tf32(rA[i].y);
                ad[2] = cvt_tf32(rA[i].z); ad[3] = cvt_tf32(rA[i].w);
                float* wd = &Ws[nxt][lrow[i]][lcol[i]];
                wd[0] = cvt_tf32(rB[i].x); wd[1] = cvt_tf32(rB[i].y);
                wd[2] = cvt_tf32(rB[i].z); wd[3] = cvt_tf32(rB[i].w);
            }
        }
        __syncthreads();
    }

    // epilogue
#pragma unroll
    for (int mt = 0; mt < 4; mt++) {
#pragma unroll
        for (int nt = 0; nt < 4; nt++) {
            size_t r0 = bm + warpM + mt * 16 + (lane >> 2);
            size_t c0 = bn + warpN + nt * 8 + (lane & 3) * 2;
            float b0 = bias ? bias[c0] : 0.f;
            float b1 = bias ? bias[c0 + 1] : 0.f;
            float v00 = acc[mt][nt][0] + b0;
            float v01 = acc[mt][nt][1] + b1;
            float v10 = acc[mt][nt][2] + b0;
            float v11 = acc[mt][nt][3] + b1;
            if (res) {
                v00 += res[r0 * (size_t)ldc + c0];
                v01 += res[r0 * (size_t)ldc + c0 + 1];
                v10 += res[(r0 + 8) * (size_t)ldc + c0];
                v11 += res[(r0 + 8) * (size_t)ldc + c0 + 1];
            }
            C[r0 * (size_t)ldc + c0] = v00;
            C[r0 * (size_t)ldc + c0 + 1] = v01;
            C[(r0 + 8) * (size_t)ldc + c0] = v10;
            C[(r0 + 8) * (size_t)ldc + c0 + 1] = v11;
        }
    }
}

// ---------------- silu(gate) * up, in place in gate ----------------
__global__ __launch_bounds__(256) void silu_mul(float* __restrict__ g,
                                                const float* __restrict__ u, int n) {
    int i = blockIdx.x * 256 + threadIdx.x;
    if (i < n) {
        float x = g[i];
        float s = 1.f / (1.f + expf(-x));
        g[i] = x * s * u[i];
    }
}

// ---------------- launch ----------------
extern "C" void kernel_launch(void* const* d_in, const int* in_sizes, int n_in,
                              void* d_out, int out_size) {
    const float* x    = (const float*)d_in[0];
    const float* cosT = (const float*)d_in[2];
    const float* sinT = (const float*)d_in[3];
    const float* wq   = (const float*)d_in[4];
    const float* bq   = (const float*)d_in[5];
    const float* wk   = (const float*)d_in[6];
    const float* bk   = (const float*)d_in[7];
    const float* wv   = (const float*)d_in[8];
    const float* bv   = (const float*)d_in[9];
    const float* wo   = (const float*)d_in[10];
    const float* qnw  = (const float*)d_in[11];
    const float* knw  = (const float*)d_in[12];
    const float* ln1  = (const float*)d_in[13];
    const float* ln2  = (const float*)d_in[14];
    const float* wg   = (const float*)d_in[15];
    const float* wu   = (const float*)d_in[16];
    const float* wd   = (const float*)d_in[17];
    float* out = (float*)d_out;

    void *ph1, *pqkv, *pattn, *px1, *pgate, *pup;
    cudaGetSymbolAddress(&ph1,  g_h1);
    cudaGetSymbolAddress(&pqkv, g_qkv);
    cudaGetSymbolAddress(&pattn,g_attn);
    cudaGetSymbolAddress(&px1,  g_x1);
    cudaGetSymbolAddress(&pgate,g_gate);
    cudaGetSymbolAddress(&pup,  g_up);
    float* h1   = (float*)ph1;
    float* qkv  = (float*)pqkv;
    float* attn = (float*)pattn;
    float* x1   = (float*)px1;
    float* gate = (float*)pgate;
    float* up   = (float*)pup;

    cudaFuncSetAttribute(attn_kernel, cudaFuncAttributeMaxDynamicSharedMemorySize, ATTN_SMEM);
    cudaFuncSetAttribute(tgemm, cudaFuncAttributeMaxDynamicSharedMemorySize, TGEMM_SMEM);

    // 1. rmsnorm1
    rmsnorm2048<<<T_TOK, 256>>>(x, ln1, h1);
    // 2. QKV projections into one [T, 3072] buffer
    tgemm<<<dim3(HID / 128, T_TOK / 128), 256, TGEMM_SMEM>>>(h1, wq, bq, nullptr, qkv,             HID, QKVW);
    tgemm<<<dim3(512 / 128, T_TOK / 128), 256, TGEMM_SMEM>>>(h1, wk, bk, nullptr, qkv + HID,       HID, QKVW);
    tgemm<<<dim3(512 / 128, T_TOK / 128), 256, TGEMM_SMEM>>>(h1, wv, bv, nullptr, qkv + HID + 512, HID, QKVW);
    // 3. per-head rmsnorm + rope (q and k heads)
    qknorm_rope<<<dim3(T_TOK, NH + NKV), 128>>>(qkv, qnw, knw, cosT, sinT);
    // 4. attention
    attn_kernel<<<dim3(BATCH * NH, SEQ / 64), 128, ATTN_SMEM>>>(qkv, attn);
    // 5. o-proj + residual -> x1
    tgemm<<<dim3(HID / 128, T_TOK / 128), 256, TGEMM_SMEM>>>(attn, wo, nullptr, x, x1, HID, HID);
    // 6. rmsnorm2 (reuse h1)
    rmsnorm2048<<<T_TOK, 256>>>(x1, ln2, h1);
    // 7. gate/up projections
    tgemm<<<dim3(INTER / 128, T_TOK / 128), 256, TGEMM_SMEM>>>(h1, wg, nullptr, nullptr, gate, HID, INTER);
    tgemm<<<dim3(INTER / 128, T_TOK / 128), 256, TGEMM_SMEM>>>(h1, wu, nullptr, nullptr, up,   HID, INTER);
    // 8. silu(gate) * up
    silu_mul<<<(T_TOK * INTER) / 256, 256>>>(gate, up, T_TOK * INTER);
    // 9. down-proj + residual -> out
    tgemm<<<dim3(HID / 128, T_TOK / 128), 256, TGEMM_SMEM>>>(gate, wd, nullptr, x1, out, INTER, HID);
}

// round 3
// speedup vs baseline: 4.0979x; 1.6261x over previous
#include <cuda_runtime.h>
#include <cuda_bf16.h>
#include <cstddef>
#include <cstdint>

// ---------------- constants ----------------
#define T_TOK   4096
#define HID     2048
#define NH      16
#define NKV     4
#define HD      128
#define INTER   8192
#define BATCH   4
#define SEQ     1024
#define QKVW    3072   // 2048 q + 512 k + 512 v
#define EPSV    1e-6f

// ---------------- scratch ----------------
__device__ float g_h1  [(size_t)T_TOK * HID];
__device__ float g_qkv [(size_t)T_TOK * QKVW];
__device__ float g_attn[(size_t)T_TOK * HID];
__device__ float g_x1  [(size_t)T_TOK * HID];
__device__ float g_gate[(size_t)T_TOK * INTER];
__device__ float g_up  [(size_t)T_TOK * INTER];

// ---------------- helpers ----------------
__device__ __forceinline__ float cvt_tf32(float x) {
    uint32_t u;
    asm("cvt.rna.tf32.f32 %0, %1;" : "=r"(u) : "f"(x));
    return __uint_as_float(u);
}
__device__ __forceinline__ uint32_t cvt_tf32u(float x) {
    uint32_t u;
    asm("cvt.rna.tf32.f32 %0, %1;" : "=r"(u) : "f"(x));
    return u;
}
__device__ __forceinline__ void mma_tf32(float* c, const uint32_t* a, const uint32_t* b) {
    asm volatile("mma.sync.aligned.m16n8k8.row.col.f32.tf32.tf32.f32 "
                 "{%0,%1,%2,%3}, {%4,%5,%6,%7}, {%8,%9}, {%0,%1,%2,%3};"
                 : "+f"(c[0]), "+f"(c[1]), "+f"(c[2]), "+f"(c[3])
                 : "r"(a[0]), "r"(a[1]), "r"(a[2]), "r"(a[3]), "r"(b[0]), "r"(b[1]));
}
__device__ __forceinline__ void ldsm_x4(uint32_t* r, uint32_t addr) {
    asm volatile("ldmatrix.sync.aligned.m8n8.x4.shared.b16 {%0,%1,%2,%3}, [%4];"
                 : "=r"(r[0]), "=r"(r[1]), "=r"(r[2]), "=r"(r[3]) : "r"(addr));
}
__device__ __forceinline__ uint32_t smem_u32(const void* p) {
    return (uint32_t)__cvta_generic_to_shared(p);
}

// ---------------- rmsnorm over 2048 cols ----------------
__global__ __launch_bounds__(256) void rmsnorm2048(const float* __restrict__ x,
                                                   const float* __restrict__ w,
                                                   float* __restrict__ y) {
    int row = blockIdx.x;
    const float* xr = x + (size_t)row * HID;
    int t = threadIdx.x;
    float vals[8];
    float ss = 0.f;
#pragma unroll
    for (int i = 0; i < 8; i++) { float v = xr[t + i * 256]; vals[i] = v; ss += v * v; }
#pragma unroll
    for (int o = 16; o > 0; o >>= 1) ss += __shfl_xor_sync(0xffffffffu, ss, o);
    __shared__ float red[8];
    __shared__ float srs;
    if ((t & 31) == 0) red[t >> 5] = ss;
    __syncthreads();
    if (t == 0) {
        float s = 0.f;
#pragma unroll
        for (int i = 0; i < 8; i++) s += red[i];
        srs = rsqrtf(s / (float)HID + EPSV);
    }
    __syncthreads();
    float r = srs;
    float* yr = y + (size_t)row * HID;
#pragma unroll
    for (int i = 0; i < 8; i++) { int c = t + i * 256; yr[c] = vals[i] * r * w[c]; }
}

// ---------------- per-head rmsnorm + RoPE ----------------
__global__ __launch_bounds__(128) void qknorm_rope(float* __restrict__ qkv,
                                                   const float* __restrict__ qnw,
                                                   const float* __restrict__ knw,
                                                   const float* __restrict__ cosT,
                                                   const float* __restrict__ sinT) {
    int tok = blockIdx.x;
    int hh  = blockIdx.y;
    int d   = threadIdx.x;
    float* base = qkv + (size_t)tok * QKVW + (hh < NH ? hh * HD : HID + (hh - NH) * HD);
    const float* nw = (hh < NH) ? qnw : knw;
    float v = base[d];
    float ss = v * v;
#pragma unroll
    for (int o = 16; o > 0; o >>= 1) ss += __shfl_xor_sync(0xffffffffu, ss, o);
    __shared__ float red[4];
    __shared__ float rtot;
    if ((d & 31) == 0) red[d >> 5] = ss;
    __syncthreads();
    if (d == 0) rtot = rsqrtf((red[0] + red[1] + red[2] + red[3]) / (float)HD + EPSV);
    __syncthreads();
    float n = v * rtot * nw[d];
    __shared__ float sn[HD];
    sn[d] = n;
    __syncthreads();
    const float* c = cosT + (size_t)tok * HD;
    const float* s = sinT + (size_t)tok * HD;
    float out = (d < 64) ? (n * c[d] - sn[d + 64] * s[d])
                         : (n * c[d] + sn[d - 64] * s[d]);
    base[d] = out;
}

// ---------------- tensor-core flash attention ----------------
// 128 q-rows per CTA, 64-k tiles, 8 warps (16 q-rows each), tf32 mma.
#define AQT 128
#define AKT 64
#define KSTR 132
#define PSTR 68
#define ATTN_SMEM ((2 * AKT * KSTR + AQT * PSTR) * 4)

__global__ __launch_bounds__(256, 1) void attn_mma(const float* __restrict__ qkv,
                                                   float* __restrict__ attn) {
    extern __shared__ float sm[];
    float* Ks = sm;                       // [64][132]
    float* Vs = Ks + AKT * KSTR;          // [64][132]
    float* Ps = Vs + AKT * KSTR;          // [128][68]
    uint32_t sKs = smem_u32(Ks);
    uint32_t sPs = smem_u32(Ps);

    int tid = threadIdx.x;
    int lane = tid & 31;
    int w = tid >> 5;
    int bh = blockIdx.x;
    int qt = blockIdx.y;
    int b = bh >> 4, h = bh & 15, kvh = h >> 2;
    int tok0 = b * SEQ + qt * AQT;
    int rowq = w * 16;
    int l4 = lane >> 2, lm = lane & 3;
    int tsel = lane >> 3, rsel = lane & 7;

    // ldmatrix lane addresses
    uint32_t kAddr[4];
#pragma unroll
    for (int p = 0; p < 4; p++) {
        int r = p * 16 + (tsel >> 1) * 8 + rsel;
        int c = (tsel & 1) * 4;
        kAddr[p] = sKs + (r * KSTR + c) * 4;
    }
    uint32_t pAddr = sPs + ((rowq + (tsel & 1) * 8 + rsel) * PSTR + (tsel >> 1) * 4) * 4;

    // Q fragments (held in registers for whole kernel), tf32-converted
    uint32_t qf[16][4];
    {
        const float* qb = qkv + (size_t)(tok0 + rowq) * QKVW + h * HD;
#pragma unroll
        for (int ks = 0; ks < 16; ks++) {
            int kc = ks * 8;
            qf[ks][0] = cvt_tf32u(qb[(size_t)l4 * QKVW + kc + lm]);
            qf[ks][1] = cvt_tf32u(qb[(size_t)(l4 + 8) * QKVW + kc + lm]);
            qf[ks][2] = cvt_tf32u(qb[(size_t)l4 * QKVW + kc + 4 + lm]);
            qf[ks][3] = cvt_tf32u(qb[(size_t)(l4 + 8) * QKVW + kc + 4 + lm]);
        }
    }

    float of[16][4];
#pragma unroll
    for (int i = 0; i < 16; i++)
#pragma unroll
        for (int j = 0; j < 4; j++) of[i][j] = 0.f;
    float mrow[2] = {-1e30f, -1e30f};
    float lsum[2] = {0.f, 0.f};
    const float scale = 0.08838834764831845f;

    int nkt = 2 * qt + 2;
    for (int kt = 0; kt < nkt; kt++) {
        __syncthreads();   // previous iteration's readers done
        // cooperative load K and V tiles (tf32-converted)
        const float* kb_ = qkv + (size_t)(b * SEQ + kt * AKT) * QKVW + HID + kvh * HD;
#pragma unroll
        for (int it = 0; it < 8; it++) {
            int i = tid + it * 256;
            int r = i >> 5, c = (i & 31) * 4;
            float4 kv4 = *(const float4*)(kb_ + (size_t)r * QKVW + c);
            float4 vv4 = *(const float4*)(kb_ + (size_t)r * QKVW + c + NKV * HD);
            float4 ko, vo;
            ko.x = cvt_tf32(kv4.x); ko.y = cvt_tf32(kv4.y);
            ko.z = cvt_tf32(kv4.z); ko.w = cvt_tf32(kv4.w);
            vo.x = cvt_tf32(vv4.x); vo.y = cvt_tf32(vv4.y);
            vo.z = cvt_tf32(vv4.z); vo.w = cvt_tf32(vv4.w);
            *(float4*)(Ks + r * KSTR + c) = ko;
            *(float4*)(Vs + r * KSTR + c) = vo;
        }
        __syncthreads();

        // S = Q @ K^T  (m16 x n64 per warp)
        float sacc[8][4];
#pragma unroll
        for (int nt = 0; nt < 8; nt++)
#pragma unroll
            for (int j = 0; j < 4; j++) sacc[nt][j] = 0.f;
#pragma unroll
        for (int ks = 0; ks < 16; ks++) {
            uint32_t bfr[4][4];
#pragma unroll
            for (int p = 0; p < 4; p++) ldsm_x4(bfr[p], kAddr[p] + ks * 32);
#pragma unroll
            for (int nt = 0; nt < 8; nt++)
                mma_tf32(sacc[nt], qf[ks], &bfr[nt >> 1][(nt & 1) * 2]);
        }

        // mask + scale
        if (kt >= 2 * qt) {
            int qg0 = qt * AQT + rowq + l4;
#pragma unroll
            for (int nt = 0; nt < 8; nt++) {
                int kg = kt * AKT + nt * 8 + 2 * lm;
                sacc[nt][0] = (kg     <= qg0    ) ? sacc[nt][0] * scale : -1e30f;
                sacc[nt][1] = (kg + 1 <= qg0    ) ? sacc[nt][1] * scale : -1e30f;
                sacc[nt][2] = (kg     <= qg0 + 8) ? sacc[nt][2] * scale : -1e30f;
                sacc[nt][3] = (kg + 1 <= qg0 + 8) ? sacc[nt][3] * scale : -1e30f;
            }
        } else {
#pragma unroll
            for (int nt = 0; nt < 8; nt++)
#pragma unroll
                for (int j = 0; j < 4; j++) sacc[nt][j] *= scale;
        }

        // online softmax (rows l4 and l4+8)
        float mx0 = -1e30f, mx1 = -1e30f;
#pragma unroll
        for (int nt = 0; nt < 8; nt++) {
            mx0 = fmaxf(mx0, fmaxf(sacc[nt][0], sacc[nt][1]));
            mx1 = fmaxf(mx1, fmaxf(sacc[nt][2], sacc[nt][3]));
        }
        mx0 = fmaxf(mx0, __shfl_xor_sync(0xffffffffu, mx0, 1));
        mx0 = fmaxf(mx0, __shfl_xor_sync(0xffffffffu, mx0, 2));
        mx1 = fmaxf(mx1, __shfl_xor_sync(0xffffffffu, mx1, 1));
        mx1 = fmaxf(mx1, __shfl_xor_sync(0xffffffffu, mx1, 2));
        float mn0 = fmaxf(mrow[0], mx0);
        float mn1 = fmaxf(mrow[1], mx1);
        float corr0 = __expf(mrow[0] - mn0);
        float corr1 = __expf(mrow[1] - mn1);
        mrow[0] = mn0; mrow[1] = mn1;

        float ps0 = 0.f, ps1 = 0.f;
#pragma unroll
        for (int nt = 0; nt < 8; nt++) {
            float p0 = __expf(sacc[nt][0] - mn0);
            float p1 = __expf(sacc[nt][1] - mn0);
            float p2 = __expf(sacc[nt][2] - mn1);
            float p3 = __expf(sacc[nt][3] - mn1);
            ps0 += p0 + p1; ps1 += p2 + p3;
            int c0 = nt * 8 + 2 * lm;
            float* pr0 = Ps + (rowq + l4) * PSTR + c0;
            float* pr1 = Ps + (rowq + l4 + 8) * PSTR + c0;
            pr0[0] = cvt_tf32(p0); pr0[1] = cvt_tf32(p1);
            pr1[0] = cvt_tf32(p2); pr1[1] = cvt_tf32(p3);
        }
        ps0 += __shfl_xor_sync(0xffffffffu, ps0, 1);
        ps0 += __shfl_xor_sync(0xffffffffu, ps0, 2);
        ps1 += __shfl_xor_sync(0xffffffffu, ps1, 1);
        ps1 += __shfl_xor_sync(0xffffffffu, ps1, 2);
        lsum[0] = lsum[0] * corr0 + ps0;
        lsum[1] = lsum[1] * corr1 + ps1;
#pragma unroll
        for (int nt2 = 0; nt2 < 16; nt2++) {
            of[nt2][0] *= corr0; of[nt2][1] *= corr0;
            of[nt2][2] *= corr1; of[nt2][3] *= corr1;
        }
        __syncthreads();   // Ps visible to this warp's ldmatrix (and all warps)

        // O += P @ V  (k = 64)
#pragma unroll
        for (int ks = 0; ks < 8; ks++) {
            uint32_t pf[4];
            ldsm_x4(pf, pAddr + ks * 32);
#pragma unroll
            for (int nt2 = 0; nt2 < 16; nt2++) {
                uint32_t vb[2];
                vb[0] = __float_as_uint(Vs[(ks * 8 + lm) * KSTR + nt2 * 8 + l4]);
                vb[1] = __float_as_uint(Vs[(ks * 8 + 4 + lm) * KSTR + nt2 * 8 + l4]);
                mma_tf32(of[nt2], pf, vb);
            }
        }
    }

    // epilogue: divide by l, store
    float inv0 = 1.f / lsum[0];
    float inv1 = 1.f / lsum[1];
    float* o0 = attn + (size_t)(tok0 + rowq + l4) * HID + h * HD;
    float* o1 = attn + (size_t)(tok0 + rowq + l4 + 8) * HID + h * HD;
#pragma unroll
    for (int nt2 = 0; nt2 < 16; nt2++) {
        int c0 = nt2 * 8 + 2 * lm;
        float2 v0 = make_float2(of[nt2][0] * inv0, of[nt2][1] * inv0);
        float2 v1 = make_float2(of[nt2][2] * inv1, of[nt2][3] * inv1);
        *(float2*)(o0 + c0) = v0;
        *(float2*)(o1 + c0) = v1;
    }
}

// ---------------- TF32 tensor-core GEMM with ldmatrix ----------------
#define GBM 128
#define GBN 128
#define GBK 32
#define KST 36
#define TGEMM_SMEM (4 * GBM * KST * 4)

__global__ __launch_bounds__(256) void tgemm(const float* __restrict__ A,
                                             const float* __restrict__ W,
                                             const float* __restrict__ bias,
                                             const float* __restrict__ res,
                                             float* __restrict__ C,
                                             int K, int ldc) {
    extern __shared__ float sm[];
    float (*As)[GBM][KST] = (float (*)[GBM][KST])sm;
    float (*Ws)[GBM][KST] = (float (*)[GBM][KST])(sm + 2 * GBM * KST);
    uint32_t sA = smem_u32(&As[0][0][0]);
    uint32_t sW = smem_u32(&Ws[0][0][0]);
    const uint32_t BUFB = GBM * KST * 4;

    int tid = threadIdx.x;
    int lane = tid & 31;
    int warp = tid >> 5;
    int warpM = (warp >> 2) * 64;
    int warpN = (warp & 3) * 32;
    size_t bm = (size_t)blockIdx.y * GBM;
    size_t bn = (size_t)blockIdx.x * GBN;
    int tsel = lane >> 3, rsel = lane & 7;

    uint32_t aAddr[4], bAddr[2];
#pragma unroll
    for (int mt = 0; mt < 4; mt++) {
        int r = warpM + mt * 16 + (tsel & 1) * 8 + rsel;
        int c = (tsel >> 1) * 4;
        aAddr[mt] = sA + (r * KST + c) * 4;
    }
#pragma unroll
    for (int p = 0; p < 2; p++) {
        int r = warpN + p * 16 + (tsel >> 1) * 8 + rsel;
        int c = (tsel & 1) * 4;
        bAddr[p] = sW + (r * KST + c) * 4;
    }

    int lrow[4], lcol[4];
#pragma unroll
    for (int i = 0; i < 4; i++) {
        int v = tid + i * 256;
        lrow[i] = v >> 3;
        lcol[i] = (v & 7) * 4;
    }

    float acc[4][4][4];
#pragma unroll
    for (int mt = 0; mt < 4; mt++)
#pragma unroll
        for (int nt = 0; nt < 4; nt++)
#pragma unroll
            for (int j = 0; j < 4; j++) acc[mt][nt][j] = 0.f;

    float4 rA[4], rB[4];
#pragma unroll
    for (int i = 0; i < 4; i++) {
        rA[i] = *(const float4*)(A + (bm + lrow[i]) * (size_t)K + lcol[i]);
        rB[i] = *(const float4*)(W + (bn + lrow[i]) * (size_t)K + lcol[i]);
    }
#pragma unroll
    for (int i = 0; i < 4; i++) {
        float* ad = &As[0][lrow[i]][lcol[i]];
        ad[0] = cvt_tf32(rA[i].x); ad[1] = cvt_tf32(rA[i].y);
        ad[2] = cvt_tf32(rA[i].z); ad[3] = cvt_tf32(rA[i].w);
        float* wd = &Ws[0][lrow[i]][lcol[i]];
        wd[0] = cvt_tf32(rB[i].x); wd[1] = cvt_tf32(rB[i].y);
        wd[2] = cvt_tf32(rB[i].z); wd[3] = cvt_tf32(rB[i].w);
    }
    __syncthreads();

    int nchunk = K / GBK;
    for (int c = 0; c < nchunk; c++) {
        int cur = c & 1;
        int nxt = cur ^ 1;
        if (c + 1 < nchunk) {
            int k0 = (c + 1) * GBK;
#pragma unroll
            for (int i = 0; i < 4; i++) {
                rA[i] = *(const float4*)(A + (bm + lrow[i]) * (size_t)K + k0 + lcol[i]);
                rB[i] = *(const float4*)(W + (bn + lrow[i]) * (size_t)K + k0 + lcol[i]);
            }
        }

        uint32_t curA = cur * BUFB;
#pragma unroll
        for (int ks = 0; ks < 4; ks++) {
            uint32_t kb4 = ks * 32;   // kb * 4 bytes
            uint32_t af[4][4], bfr[2][4];
#pragma unroll
            for (int mt = 0; mt < 4; mt++) ldsm_x4(af[mt], aAddr[mt] + curA + kb4);
#pragma unroll
            for (int p = 0; p < 2; p++) ldsm_x4(bfr[p], bAddr[p] + curA + kb4);
#pragma unroll
            for (int mt = 0; mt < 4; mt++)
#pragma unroll
                for (int nt = 0; nt < 4; nt++)
                    mma_tf32(acc[mt][nt], af[mt], &bfr[nt >> 1][(nt & 1) * 2]);
        }

        if (c + 1 < nchunk) {
#pragma unroll
            for (int i = 0; i < 4; i++) {
                float* ad = &As[nxt][lrow[i]][lcol[i]];
                ad[0] = cvt_tf32(rA[i].x); ad[1] = cvt_tf32(rA[i].y);
                ad[2] = cvt_tf32(rA[i].z); ad[3] = cvt_tf32(rA[i].w);
                float* wd = &Ws[nxt][lrow[i]][lcol[i]];
                wd[0] = cvt_tf32(rB[i].x); wd[1] = cvt_tf32(rB[i].y);
                wd[2] = cvt_tf32(rB[i].z); wd[3] = cvt_tf32(rB[i].w);
            }
        }
        __syncthreads();
    }

#pragma unroll
    for (int mt = 0; mt < 4; mt++) {
#pragma unroll
        for (int nt = 0; nt < 4; nt++) {
            size_t r0 = bm + warpM + mt * 16 + (lane >> 2);
            size_t c0 = bn + warpN + nt * 8 + (lane & 3) * 2;
            float b0 = bias ? bias[c0] : 0.f;
            float b1 = bias ? bias[c0 + 1] : 0.f;
            float v00 = acc[mt][nt][0] + b0;
            float v01 = acc[mt][nt][1] + b1;
            float v10 = acc[mt][nt][2] + b0;
            float v11 = acc[mt][nt][3] + b1;
            if (res) {
                v00 += res[r0 * (size_t)ldc + c0];
                v01 += res[r0 * (size_t)ldc + c0 + 1];
                v10 += res[(r0 + 8) * (size_t)ldc + c0];
                v11 += res[(r0 + 8) * (size_t)ldc + c0 + 1];
            }
            C[r0 * (size_t)ldc + c0] = v00;
            C[r0 * (size_t)ldc + c0 + 1] = v01;
            C[(r0 + 8) * (size_t)ldc + c0] = v10;
            C[(r0 + 8) * (size_t)ldc + c0 + 1] = v11;
        }
    }
}

// ---------------- silu(gate) * up ----------------
__global__ __launch_bounds__(256) void silu_mul(float* __restrict__ g,
                                                const float* __restrict__ u, int n) {
    int i = blockIdx.x * 256 + threadIdx.x;
    if (i < n) {
        float x = g[i];
        float s = 1.f / (1.f + expf(-x));
        g[i] = x * s * u[i];
    }
}

// ---------------- launch ----------------
extern "C" void kernel_launch(void* const* d_in, const int* in_sizes, int n_in,
                              void* d_out, int out_size) {
    const float* x    = (const float*)d_in[0];
    const float* cosT = (const float*)d_in[2];
    const float* sinT = (const float*)d_in[3];
    const float* wq   = (const float*)d_in[4];
    const float* bq   = (const float*)d_in[5];
    const float* wk   = (const float*)d_in[6];
    const float* bk   = (const float*)d_in[7];
    const float* wv   = (const float*)d_in[8];
    const float* bv   = (const float*)d_in[9];
    const float* wo   = (const float*)d_in[10];
    const float* qnw  = (const float*)d_in[11];
    const float* knw  = (const float*)d_in[12];
    const float* ln1  = (const float*)d_in[13];
    const float* ln2  = (const float*)d_in[14];
    const float* wg   = (const float*)d_in[15];
    const float* wu   = (const float*)d_in[16];
    const float* wd   = (const float*)d_in[17];
    float* out = (float*)d_out;

    void *ph1, *pqkv, *pattn, *px1, *pgate, *pup;
    cudaGetSymbolAddress(&ph1,  g_h1);
    cudaGetSymbolAddress(&pqkv, g_qkv);
    cudaGetSymbolAddress(&pattn,g_attn);
    cudaGetSymbolAddress(&px1,  g_x1);
    cudaGetSymbolAddress(&pgate,g_gate);
    cudaGetSymbolAddress(&pup,  g_up);
    float* h1   = (float*)ph1;
    float* qkv  = (float*)pqkv;
    float* attn = (float*)pattn;
    float* x1   = (float*)px1;
    float* gate = (float*)pgate;
    float* up   = (float*)pup;

    cudaFuncSetAttribute(attn_mma, cudaFuncAttributeMaxDynamicSharedMemorySize, ATTN_SMEM);
    cudaFuncSetAttribute(tgemm, cudaFuncAttributeMaxDynamicSharedMemorySize, TGEMM_SMEM);

    rmsnorm2048<<<T_TOK, 256>>>(x, ln1, h1);
    tgemm<<<dim3(HID / 128, T_TOK / 128), 256, TGEMM_SMEM>>>(h1, wq, bq, nullptr, qkv,             HID, QKVW);
    tgemm<<<dim3(512 / 128, T_TOK / 128), 256, TGEMM_SMEM>>>(h1, wk, bk, nullptr, qkv + HID,       HID, QKVW);
    tgemm<<<dim3(512 / 128, T_TOK / 128), 256, TGEMM_SMEM>>>(h1, wv, bv, nullptr, qkv + HID + 512, HID, QKVW);
    qknorm_rope<<<dim3(T_TOK, NH + NKV), 128>>>(qkv, qnw, knw, cosT, sinT);
    attn_mma<<<dim3(BATCH * NH, SEQ / AQT), 256, ATTN_SMEM>>>(qkv, attn);
    tgemm<<<dim3(HID / 128, T_TOK / 128), 256, TGEMM_SMEM>>>(attn, wo, nullptr, x, x1, HID, HID);
    rmsnorm2048<<<T_TOK, 256>>>(x1, ln2, h1);
    tgemm<<<dim3(INTER / 128, T_TOK / 128), 256, TGEMM_SMEM>>>(h1, wg, nullptr, nullptr, gate, HID, INTER);
    tgemm<<<dim3(INTER / 128, T_TOK / 128), 256, TGEMM_SMEM>>>(h1, wu, nullptr, nullptr, up,   HID, INTER);
    silu_mul<<<(T_TOK * INTER) / 256, 256>>>(gate, up, T_TOK * INTER);
    tgemm<<<dim3(HID / 128, T_TOK / 128), 256, TGEMM_SMEM>>>(gate, wd, nullptr, x1, out, INTER, HID);
}

// round 4
// speedup vs baseline: 4.1312x; 1.0081x over previous
#include <cuda_runtime.h>
#include <cuda_bf16.h>
#include <cstddef>
#include <cstdint>

// ---------------- constants ----------------
#define T_TOK   4096
#define HID     2048
#define NH      16
#define NKV     4
#define HD      128
#define INTER   8192
#define BATCH   4
#define SEQ     1024
#define QKVW    3072   // 2048 q + 512 k + 512 v
#define EPSV    1e-6f

// ---------------- scratch ----------------
__device__ float g_h1  [(size_t)T_TOK * HID];
__device__ float g_qkv [(size_t)T_TOK * QKVW];
__device__ float g_attn[(size_t)T_TOK * HID];
__device__ float g_x1  [(size_t)T_TOK * HID];
__device__ float g_gate[(size_t)T_TOK * INTER];
__device__ float g_up  [(size_t)T_TOK * INTER];

// ---------------- helpers ----------------
__device__ __forceinline__ float cvt_tf32(float x) {
    uint32_t u;
    asm("cvt.rna.tf32.f32 %0, %1;" : "=r"(u) : "f"(x));
    return __uint_as_float(u);
}
__device__ __forceinline__ uint32_t cvt_tf32u(float x) {
    uint32_t u;
    asm("cvt.rna.tf32.f32 %0, %1;" : "=r"(u) : "f"(x));
    return u;
}
__device__ __forceinline__ void mma_tf32(float* c, const uint32_t* a, const uint32_t* b) {
    asm volatile("mma.sync.aligned.m16n8k8.row.col.f32.tf32.tf32.f32 "
                 "{%0,%1,%2,%3}, {%4,%5,%6,%7}, {%8,%9}, {%0,%1,%2,%3};"
                 : "+f"(c[0]), "+f"(c[1]), "+f"(c[2]), "+f"(c[3])
                 : "r"(a[0]), "r"(a[1]), "r"(a[2]), "r"(a[3]), "r"(b[0]), "r"(b[1]));
}
__device__ __forceinline__ void ldsm_x4(uint32_t* r, uint32_t addr) {
    asm volatile("ldmatrix.sync.aligned.m8n8.x4.shared.b16 {%0,%1,%2,%3}, [%4];"
                 : "=r"(r[0]), "=r"(r[1]), "=r"(r[2]), "=r"(r[3]) : "r"(addr));
}
__device__ __forceinline__ uint32_t smem_u32(const void* p) {
    return (uint32_t)__cvta_generic_to_shared(p);
}

// ---------------- rmsnorm over 2048 cols ----------------
__global__ __launch_bounds__(256) void rmsnorm2048(const float* __restrict__ x,
                                                   const float* __restrict__ w,
                                                   float* __restrict__ y) {
    int row = blockIdx.x;
    const float* xr = x + (size_t)row * HID;
    int t = threadIdx.x;
    float vals[8];
    float ss = 0.f;
#pragma unroll
    for (int i = 0; i < 8; i++) { float v = xr[t + i * 256]; vals[i] = v; ss += v * v; }
#pragma unroll
    for (int o = 16; o > 0; o >>= 1) ss += __shfl_xor_sync(0xffffffffu, ss, o);
    __shared__ float red[8];
    __shared__ float srs;
    if ((t & 31) == 0) red[t >> 5] = ss;
    __syncthreads();
    if (t == 0) {
        float s = 0.f;
#pragma unroll
        for (int i = 0; i < 8; i++) s += red[i];
        srs = rsqrtf(s / (float)HID + EPSV);
    }
    __syncthreads();
    float r = srs;
    float* yr = y + (size_t)row * HID;
#pragma unroll
    for (int i = 0; i < 8; i++) { int c = t + i * 256; yr[c] = vals[i] * r * w[c]; }
}

// ---------------- per-head rmsnorm + RoPE ----------------
__global__ __launch_bounds__(128) void qknorm_rope(float* __restrict__ qkv,
                                                   const float* __restrict__ qnw,
                                                   const float* __restrict__ knw,
                                                   const float* __restrict__ cosT,
                                                   const float* __restrict__ sinT) {
    int tok = blockIdx.x;
    int hh  = blockIdx.y;
    int d   = threadIdx.x;
    float* base = qkv + (size_t)tok * QKVW + (hh < NH ? hh * HD : HID + (hh - NH) * HD);
    const float* nw = (hh < NH) ? qnw : knw;
    float v = base[d];
    float ss = v * v;
#pragma unroll
    for (int o = 16; o > 0; o >>= 1) ss += __shfl_xor_sync(0xffffffffu, ss, o);
    __shared__ float red[4];
    __shared__ float rtot;
    if ((d & 31) == 0) red[d >> 5] = ss;
    __syncthreads();
    if (d == 0) rtot = rsqrtf((red[0] + red[1] + red[2] + red[3]) / (float)HD + EPSV);
    __syncthreads();
    float n = v * rtot * nw[d];
    __shared__ float sn[HD];
    sn[d] = n;
    __syncthreads();
    const float* c = cosT + (size_t)tok * HD;
    const float* s = sinT + (size_t)tok * HD;
    float out = (d < 64) ? (n * c[d] - sn[d + 64] * s[d])
                         : (n * c[d] + sn[d - 64] * s[d]);
    base[d] = out;
}

// ---------------- tensor-core flash attention ----------------
#define AQT 128
#define AKT 64
#define KSTR 132
#define PSTR 68
#define ATTN_SMEM ((2 * AKT * KSTR + AQT * PSTR) * 4)

__global__ __launch_bounds__(256, 1) void attn_mma(const float* __restrict__ qkv,
                                                   float* __restrict__ attn) {
    extern __shared__ float sm[];
    float* Ks = sm;
    float* Vs = Ks + AKT * KSTR;
    float* Ps = Vs + AKT * KSTR;
    uint32_t sKs = smem_u32(Ks);
    uint32_t sPs = smem_u32(Ps);

    int tid = threadIdx.x;
    int lane = tid & 31;
    int w = tid >> 5;
    int bh = blockIdx.x;
    int qt = blockIdx.y;
    int b = bh >> 4, h = bh & 15, kvh = h >> 2;
    int tok0 = b * SEQ + qt * AQT;
    int rowq = w * 16;
    int l4 = lane >> 2, lm = lane & 3;
    int tsel = lane >> 3, rsel = lane & 7;

    uint32_t kAddr[4];
#pragma unroll
    for (int p = 0; p < 4; p++) {
        int r = p * 16 + (tsel >> 1) * 8 + rsel;
        int c = (tsel & 1) * 4;
        kAddr[p] = sKs + (r * KSTR + c) * 4;
    }
    uint32_t pAddr = sPs + ((rowq + (tsel & 1) * 8 + rsel) * PSTR + (tsel >> 1) * 4) * 4;

    uint32_t qf[16][4];
    {
        const float* qb = qkv + (size_t)(tok0 + rowq) * QKVW + h * HD;
#pragma unroll
        for (int ks = 0; ks < 16; ks++) {
            int kc = ks * 8;
            qf[ks][0] = cvt_tf32u(qb[(size_t)l4 * QKVW + kc + lm]);
            qf[ks][1] = cvt_tf32u(qb[(size_t)(l4 + 8) * QKVW + kc + lm]);
            qf[ks][2] = cvt_tf32u(qb[(size_t)l4 * QKVW + kc + 4 + lm]);
            qf[ks][3] = cvt_tf32u(qb[(size_t)(l4 + 8) * QKVW + kc + 4 + lm]);
        }
    }

    float of[16][4];
#pragma unroll
    for (int i = 0; i < 16; i++)
#pragma unroll
        for (int j = 0; j < 4; j++) of[i][j] = 0.f;
    float mrow[2] = {-1e30f, -1e30f};
    float lsum[2] = {0.f, 0.f};
    const float scale = 0.08838834764831845f;

    int nkt = 2 * qt + 2;
    for (int kt = 0; kt < nkt; kt++) {
        __syncthreads();
        const float* kb_ = qkv + (size_t)(b * SEQ + kt * AKT) * QKVW + HID + kvh * HD;
#pragma unroll
        for (int it = 0; it < 8; it++) {
            int i = tid + it * 256;
            int r = i >> 5, c = (i & 31) * 4;
            float4 kv4 = *(const float4*)(kb_ + (size_t)r * QKVW + c);
            float4 vv4 = *(const float4*)(kb_ + (size_t)r * QKVW + c + NKV * HD);
            float4 ko, vo;
            ko.x = cvt_tf32(kv4.x); ko.y = cvt_tf32(kv4.y);
            ko.z = cvt_tf32(kv4.z); ko.w = cvt_tf32(kv4.w);
            vo.x = cvt_tf32(vv4.x); vo.y = cvt_tf32(vv4.y);
            vo.z = cvt_tf32(vv4.z); vo.w = cvt_tf32(vv4.w);
            *(float4*)(Ks + r * KSTR + c) = ko;
            *(float4*)(Vs + r * KSTR + c) = vo;
        }
        __syncthreads();

        float sacc[8][4];
#pragma unroll
        for (int nt = 0; nt < 8; nt++)
#pragma unroll
            for (int j = 0; j < 4; j++) sacc[nt][j] = 0.f;
#pragma unroll
        for (int ks = 0; ks < 16; ks++) {
            uint32_t bfr[4][4];
#pragma unroll
            for (int p = 0; p < 4; p++) ldsm_x4(bfr[p], kAddr[p] + ks * 32);
#pragma unroll
            for (int nt = 0; nt < 8; nt++)
                mma_tf32(sacc[nt], qf[ks], &bfr[nt >> 1][(nt & 1) * 2]);
        }

        if (kt >= 2 * qt) {
            int qg0 = qt * AQT + rowq + l4;
#pragma unroll
            for (int nt = 0; nt < 8; nt++) {
                int kg = kt * AKT + nt * 8 + 2 * lm;
                sacc[nt][0] = (kg     <= qg0    ) ? sacc[nt][0] * scale : -1e30f;
                sacc[nt][1] = (kg + 1 <= qg0    ) ? sacc[nt][1] * scale : -1e30f;
                sacc[nt][2] = (kg     <= qg0 + 8) ? sacc[nt][2] * scale : -1e30f;
                sacc[nt][3] = (kg + 1 <= qg0 + 8) ? sacc[nt][3] * scale : -1e30f;
            }
        } else {
#pragma unroll
            for (int nt = 0; nt < 8; nt++)
#pragma unroll
                for (int j = 0; j < 4; j++) sacc[nt][j] *= scale;
        }

        float mx0 = -1e30f, mx1 = -1e30f;
#pragma unroll
        for (int nt = 0; nt < 8; nt++) {
            mx0 = fmaxf(mx0, fmaxf(sacc[nt][0], sacc[nt][1]));
            mx1 = fmaxf(mx1, fmaxf(sacc[nt][2], sacc[nt][3]));
        }
        mx0 = fmaxf(mx0, __shfl_xor_sync(0xffffffffu, mx0, 1));
        mx0 = fmaxf(mx0, __shfl_xor_sync(0xffffffffu, mx0, 2));
        mx1 = fmaxf(mx1, __shfl_xor_sync(0xffffffffu, mx1, 1));
        mx1 = fmaxf(mx1, __shfl_xor_sync(0xffffffffu, mx1, 2));
        float mn0 = fmaxf(mrow[0], mx0);
        float mn1 = fmaxf(mrow[1], mx1);
        float corr0 = __expf(mrow[0] - mn0);
        float corr1 = __expf(mrow[1] - mn1);
        mrow[0] = mn0; mrow[1] = mn1;

        float ps0 = 0.f, ps1 = 0.f;
#pragma unroll
        for (int nt = 0; nt < 8; nt++) {
            float p0 = __expf(sacc[nt][0] - mn0);
            float p1 = __expf(sacc[nt][1] - mn0);
            float p2 = __expf(sacc[nt][2] - mn1);
            float p3 = __expf(sacc[nt][3] - mn1);
            ps0 += p0 + p1; ps1 += p2 + p3;
            int c0 = nt * 8 + 2 * lm;
            float* pr0 = Ps + (rowq + l4) * PSTR + c0;
            float* pr1 = Ps + (rowq + l4 + 8) * PSTR + c0;
            pr0[0] = cvt_tf32(p0); pr0[1] = cvt_tf32(p1);
            pr1[0] = cvt_tf32(p2); pr1[1] = cvt_tf32(p3);
        }
        ps0 += __shfl_xor_sync(0xffffffffu, ps0, 1);
        ps0 += __shfl_xor_sync(0xffffffffu, ps0, 2);
        ps1 += __shfl_xor_sync(0xffffffffu, ps1, 1);
        ps1 += __shfl_xor_sync(0xffffffffu, ps1, 2);
        lsum[0] = lsum[0] * corr0 + ps0;
        lsum[1] = lsum[1] * corr1 + ps1;
#pragma unroll
        for (int nt2 = 0; nt2 < 16; nt2++) {
            of[nt2][0] *= corr0; of[nt2][1] *= corr0;
            of[nt2][2] *= corr1; of[nt2][3] *= corr1;
        }
        __syncthreads();

#pragma unroll
        for (int ks = 0; ks < 8; ks++) {
            uint32_t pf[4];
            ldsm_x4(pf, pAddr + ks * 32);
#pragma unroll
            for (int nt2 = 0; nt2 < 16; nt2++) {
                uint32_t vb[2];
                vb[0] = __float_as_uint(Vs[(ks * 8 + lm) * KSTR + nt2 * 8 + l4]);
                vb[1] = __float_as_uint(Vs[(ks * 8 + 4 + lm) * KSTR + nt2 * 8 + l4]);
                mma_tf32(of[nt2], pf, vb);
            }
        }
    }

    float inv0 = 1.f / lsum[0];
    float inv1 = 1.f / lsum[1];
    float* o0 = attn + (size_t)(tok0 + rowq + l4) * HID + h * HD;
    float* o1 = attn + (size_t)(tok0 + rowq + l4 + 8) * HID + h * HD;
#pragma unroll
    for (int nt2 = 0; nt2 < 16; nt2++) {
        int c0 = nt2 * 8 + 2 * lm;
        float2 v0 = make_float2(of[nt2][0] * inv0, of[nt2][1] * inv0);
        float2 v1 = make_float2(of[nt2][2] * inv1, of[nt2][3] * inv1);
        *(float2*)(o0 + c0) = v0;
        *(float2*)(o1 + c0) = v1;
    }
}

// ---------------- TF32 tensor-core GEMM body ----------------
#define GBM 128
#define GBN 128
#define GBK 32
#define KST 36
#define TGEMM_SMEM (4 * GBM * KST * 4)

// C[bm:bm+128, bnC:bnC+128] = A[bm:,:K] @ W[bnW:bnW+128,:K]^T (+bias[bnW:])(+res)
__device__ __forceinline__ void gemm_body(const float* __restrict__ A,
                                          const float* __restrict__ W,
                                          const float* __restrict__ bias,
                                          const float* __restrict__ res,
                                          float* __restrict__ C,
                                          int K, int ldc,
                                          size_t bm, size_t bnW, size_t bnC,
                                          float* sm) {
    float (*As)[GBM][KST] = (float (*)[GBM][KST])sm;
    float (*Ws)[GBM][KST] = (float (*)[GBM][KST])(sm + 2 * GBM * KST);
    uint32_t sA = smem_u32(&As[0][0][0]);
    uint32_t sW = smem_u32(&Ws[0][0][0]);
    const uint32_t BUFB = GBM * KST * 4;

    int tid = threadIdx.x;
    int lane = tid & 31;
    int warp = tid >> 5;
    int warpM = (warp >> 2) * 64;
    int warpN = (warp & 3) * 32;
    int tsel = lane >> 3, rsel = lane & 7;

    uint32_t aAddr[4], bAddr[2];
#pragma unroll
    for (int mt = 0; mt < 4; mt++) {
        int r = warpM + mt * 16 + (tsel & 1) * 8 + rsel;
        int c = (tsel >> 1) * 4;
        aAddr[mt] = sA + (r * KST + c) * 4;
    }
#pragma unroll
    for (int p = 0; p < 2; p++) {
        int r = warpN + p * 16 + (tsel >> 1) * 8 + rsel;
        int c = (tsel & 1) * 4;
        bAddr[p] = sW + (r * KST + c) * 4;
    }

    int lrow[4], lcol[4];
#pragma unroll
    for (int i = 0; i < 4; i++) {
        int v = tid + i * 256;
        lrow[i] = v >> 3;
        lcol[i] = (v & 7) * 4;
    }

    float acc[4][4][4];
#pragma unroll
    for (int mt = 0; mt < 4; mt++)
#pragma unroll
        for (int nt = 0; nt < 4; nt++)
#pragma unroll
            for (int j = 0; j < 4; j++) acc[mt][nt][j] = 0.f;

    float4 rA[4], rB[4];
#pragma unroll
    for (int i = 0; i < 4; i++) {
        rA[i] = *(const float4*)(A + (bm + lrow[i]) * (size_t)K + lcol[i]);
        rB[i] = *(const float4*)(W + (bnW + lrow[i]) * (size_t)K + lcol[i]);
    }
#pragma unroll
    for (int i = 0; i < 4; i++) {
        float4 av, wv;
        av.x = cvt_tf32(rA[i].x); av.y = cvt_tf32(rA[i].y);
        av.z = cvt_tf32(rA[i].z); av.w = cvt_tf32(rA[i].w);
        wv.x = cvt_tf32(rB[i].x); wv.y = cvt_tf32(rB[i].y);
        wv.z = cvt_tf32(rB[i].z); wv.w = cvt_tf32(rB[i].w);
        *(float4*)&As[0][lrow[i]][lcol[i]] = av;
        *(float4*)&Ws[0][lrow[i]][lcol[i]] = wv;
    }
    __syncthreads();

    int nchunk = K / GBK;
    for (int c = 0; c < nchunk; c++) {
        int cur = c & 1;
        int nxt = cur ^ 1;
        if (c + 1 < nchunk) {
            int k0 = (c + 1) * GBK;
#pragma unroll
            for (int i = 0; i < 4; i++) {
                rA[i] = *(const float4*)(A + (bm + lrow[i]) * (size_t)K + k0 + lcol[i]);
                rB[i] = *(const float4*)(W + (bnW + lrow[i]) * (size_t)K + k0 + lcol[i]);
            }
        }

        uint32_t curA = cur * BUFB;
#pragma unroll
        for (int ks = 0; ks < 4; ks++) {
            uint32_t kb4 = ks * 32;
            uint32_t af[4][4], bfr[2][4];
#pragma unroll
            for (int mt = 0; mt < 4; mt++) ldsm_x4(af[mt], aAddr[mt] + curA + kb4);
#pragma unroll
            for (int p = 0; p < 2; p++) ldsm_x4(bfr[p], bAddr[p] + curA + kb4);
#pragma unroll
            for (int mt = 0; mt < 4; mt++)
#pragma unroll
                for (int nt = 0; nt < 4; nt++)
                    mma_tf32(acc[mt][nt], af[mt], &bfr[nt >> 1][(nt & 1) * 2]);
        }

        if (c + 1 < nchunk) {
#pragma unroll
            for (int i = 0; i < 4; i++) {
                float4 av, wv;
                av.x = cvt_tf32(rA[i].x); av.y = cvt_tf32(rA[i].y);
                av.z = cvt_tf32(rA[i].z); av.w = cvt_tf32(rA[i].w);
                wv.x = cvt_tf32(rB[i].x); wv.y = cvt_tf32(rB[i].y);
                wv.z = cvt_tf32(rB[i].z); wv.w = cvt_tf32(rB[i].w);
                *(float4*)&As[nxt][lrow[i]][lcol[i]] = av;
                *(float4*)&Ws[nxt][lrow[i]][lcol[i]] = wv;
            }
        }
        __syncthreads();
    }

#pragma unroll
    for (int mt = 0; mt < 4; mt++) {
#pragma unroll
        for (int nt = 0; nt < 4; nt++) {
            size_t r0 = bm + warpM + mt * 16 + (lane >> 2);
            size_t cW = bnW + warpN + nt * 8 + (lane & 3) * 2;
            size_t cC = bnC + warpN + nt * 8 + (lane & 3) * 2;
            float b0 = bias ? bias[cW] : 0.f;
            float b1 = bias ? bias[cW + 1] : 0.f;
            float v00 = acc[mt][nt][0] + b0;
            float v01 = acc[mt][nt][1] + b1;
            float v10 = acc[mt][nt][2] + b0;
            float v11 = acc[mt][nt][3] + b1;
            if (res) {
                v00 += res[r0 * (size_t)ldc + cC];
                v01 += res[r0 * (size_t)ldc + cC + 1];
                v10 += res[(r0 + 8) * (size_t)ldc + cC];
                v11 += res[(r0 + 8) * (size_t)ldc + cC + 1];
            }
            *(float2*)(C + r0 * (size_t)ldc + cC) = make_float2(v00, v01);
            *(float2*)(C + (r0 + 8) * (size_t)ldc + cC) = make_float2(v10, v11);
        }
    }
}

// generic gemm
__global__ __launch_bounds__(256, 2) void tgemm(const float* __restrict__ A,
                                                const float* __restrict__ W,
                                                const float* __restrict__ bias,
                                                const float* __restrict__ res,
                                                float* __restrict__ C,
                                                int K, int ldc) {
    extern __shared__ float sm[];
    size_t bn = (size_t)blockIdx.x * GBN;
    gemm_body(A, W, bias, res, C, K, ldc, (size_t)blockIdx.y * GBM, bn, bn, sm);
}

// fused QKV projection: nblocks 0-15 q, 16-19 k, 20-23 v
__global__ __launch_bounds__(256, 2) void qkv_gemm(const float* __restrict__ A,
                                                   const float* __restrict__ wq,
                                                   const float* __restrict__ bq,
                                                   const float* __restrict__ wk,
                                                   const float* __restrict__ bk,
                                                   const float* __restrict__ wv,
                                                   const float* __restrict__ bv,
                                                   float* __restrict__ qkv) {
    extern __shared__ float sm[];
    int nb = blockIdx.x;
    const float* W; const float* bias; size_t bnW, bnC;
    if (nb < 16)      { W = wq; bias = bq; bnW = (size_t)nb * 128;        bnC = bnW; }
    else if (nb < 20) { W = wk; bias = bk; bnW = (size_t)(nb - 16) * 128; bnC = 2048 + bnW; }
    else              { W = wv; bias = bv; bnW = (size_t)(nb - 20) * 128; bnC = 2560 + bnW; }
    gemm_body(A, W, bias, nullptr, qkv, HID, QKVW, (size_t)blockIdx.y * GBM, bnW, bnC, sm);
}

// fused gate+up projection: nblocks 0-63 gate, 64-127 up
__global__ __launch_bounds__(256, 2) void gateup_gemm(const float* __restrict__ A,
                                                      const float* __restrict__ wg,
                                                      const float* __restrict__ wu,
                                                      float* __restrict__ gate,
                                                      float* __restrict__ up) {
    extern __shared__ float sm[];
    int nb = blockIdx.x;
    const float* W; float* C; size_t bn;
    if (nb < 64) { W = wg; C = gate; bn = (size_t)nb * 128; }
    else         { W = wu; C = up;   bn = (size_t)(nb - 64) * 128; }
    gemm_body(A, W, nullptr, nullptr, C, HID, INTER, (size_t)blockIdx.y * GBM, bn, bn, sm);
}

// ---------------- silu(gate) * up ----------------
__global__ __launch_bounds__(256) void silu_mul(float* __restrict__ g,
                                                const float* __restrict__ u, int n) {
    int i = blockIdx.x * 256 + threadIdx.x;
    if (i < n) {
        float x = g[i];
        float s = 1.f / (1.f + expf(-x));
        g[i] = x * s * u[i];
    }
}

// ---------------- launch ----------------
extern "C" void kernel_launch(void* const* d_in, const int* in_sizes, int n_in,
                              void* d_out, int out_size) {
    const float* x    = (const float*)d_in[0];
    const float* cosT = (const float*)d_in[2];
    const float* sinT = (const float*)d_in[3];
    const float* wq   = (const float*)d_in[4];
    const float* bq   = (const float*)d_in[5];
    const float* wk   = (const float*)d_in[6];
    const float* bk   = (const float*)d_in[7];
    const float* wv   = (const float*)d_in[8];
    const float* bv   = (const float*)d_in[9];
    const float* wo   = (const float*)d_in[10];
    const float* qnw  = (const float*)d_in[11];
    const float* knw  = (const float*)d_in[12];
    const float* ln1  = (const float*)d_in[13];
    const float* ln2  = (const float*)d_in[14];
    const float* wg   = (const float*)d_in[15];
    const float* wu   = (const float*)d_in[16];
    const float* wd   = (const float*)d_in[17];
    float* out = (float*)d_out;

    void *ph1, *pqkv, *pattn, *px1, *pgate, *pup;
    cudaGetSymbolAddress(&ph1,  g_h1);
    cudaGetSymbolAddress(&pqkv, g_qkv);
    cudaGetSymbolAddress(&pattn,g_attn);
    cudaGetSymbolAddress(&px1,  g_x1);
    cudaGetSymbolAddress(&pgate,g_gate);
    cudaGetSymbolAddress(&pup,  g_up);
    float* h1   = (float*)ph1;
    float* qkv  = (float*)pqkv;
    float* attn = (float*)pattn;
    float* x1   = (float*)px1;
    float* gate = (float*)pgate;
    float* up   = (float*)pup;

    cudaFuncSetAttribute(attn_mma, cudaFuncAttributeMaxDynamicSharedMemorySize, ATTN_SMEM);
    cudaFuncSetAttribute(tgemm, cudaFuncAttributeMaxDynamicSharedMemorySize, TGEMM_SMEM);
    cudaFuncSetAttribute(qkv_gemm, cudaFuncAttributeMaxDynamicSharedMemorySize, TGEMM_SMEM);
    cudaFuncSetAttribute(gateup_gemm, cudaFuncAttributeMaxDynamicSharedMemorySize, TGEMM_SMEM);

    rmsnorm2048<<<T_TOK, 256>>>(x, ln1, h1);
    qkv_gemm<<<dim3(24, T_TOK / 128), 256, TGEMM_SMEM>>>(h1, wq, bq, wk, bk, wv, bv, qkv);
    qknorm_rope<<<dim3(T_TOK, NH + NKV), 128>>>(qkv, qnw, knw, cosT, sinT);
    attn_mma<<<dim3(BATCH * NH, SEQ / AQT), 256, ATTN_SMEM>>>(qkv, attn);
    tgemm<<<dim3(HID / 128, T_TOK / 128), 256, TGEMM_SMEM>>>(attn, wo, nullptr, x, x1, HID, HID);
    rmsnorm2048<<<T_TOK, 256>>>(x1, ln2, h1);
    gateup_gemm<<<dim3(128, T_TOK / 128), 256, TGEMM_SMEM>>>(h1, wg, wu, gate, up);
    silu_mul<<<(T_TOK * INTER) / 256, 256>>>(gate, up, T_TOK * INTER);
    tgemm<<<dim3(HID / 128, T_TOK / 128), 256, TGEMM_SMEM>>>(gate, wd, nullptr, x1, out, INTER, HID);
}